// round 2
// baseline (speedup 1.0000x reference)
#include <cuda_runtime.h>
#include <cstdint>

// Problem constants
#define BB   2
#define JJ   24
#define DD   32
#define NV   32768           // 32*32*32
#define PX2D (JJ*DD)         // 768

typedef unsigned long long u64;

// ---------------------------------------------------------------------------
// f32x2 packed helpers (sm_100+ PTX)
// ---------------------------------------------------------------------------
__device__ __forceinline__ void fma2(u64 &acc, u64 a, u64 b) {
    asm("fma.rn.f32x2 %0, %1, %2, %0;" : "+l"(acc) : "l"(a), "l"(b));
}
// Q = (hi(a), lo(b))
__device__ __forceinline__ u64 mkq(u64 a, u64 b) {
    u64 r;
    asm("{ .reg .b32 x,y,z,w;\n\t"
        "mov.b64 {x,y}, %1;\n\t"
        "mov.b64 {z,w}, %2;\n\t"
        "mov.b64 %0, {y,z}; }"
        : "=l"(r) : "l"(a), "l"(b));
    return r;
}
__device__ __forceinline__ void unpack2(u64 v, float &lo, float &hi) {
    asm("mov.b64 {%0,%1}, %2;" : "=f"(lo), "=f"(hi) : "l"(v));
}

// ---------------------------------------------------------------------------
// Scratch (device globals; no allocation allowed)
// ---------------------------------------------------------------------------
__device__ float g_x2d[BB*7*PX2D];   // [dual(0..4), evalop1(5), g(6)]
__device__ float g_h2a[BB*32*PX2D];
__device__ float g_h2b[BB*32*PX2D];
__device__ float g_y3d[BB*6*NV];     // [primal(0..4), evalop2(5)]
__device__ float g_h3a[BB*32*NV];
__device__ float g_h3b[BB*32*NV];
__device__ float g_f  [BB*NV];       // Fortran-flattened primal channel 1

// ---------------------------------------------------------------------------
// Init: dual -> x2d[0..4], g -> x2d[6], primal -> y3d[0..4]
// ---------------------------------------------------------------------------
__global__ void init_kernel(const float* __restrict__ dual,
                            const float* __restrict__ gg,
                            const float* __restrict__ primal) {
    int i = blockIdx.x * blockDim.x + threadIdx.x;
    if (i < BB*5*NV) {
        int b = i / (5*NV); int r = i % (5*NV); int c = r / NV; int v = r % NV;
        g_y3d[(size_t)(b*6 + c)*NV + v] = primal[i];
    }
    if (i < BB*5*PX2D) {
        int b = i / (5*PX2D); int r = i % (5*PX2D); int c = r / PX2D; int p = r % PX2D;
        g_x2d[(size_t)(b*7 + c)*PX2D + p] = dual[i];
    }
    if (i < BB*PX2D) {
        int b = i / PX2D; int p = i % PX2D;
        g_x2d[(size_t)(b*7 + 6)*PX2D + p] = gg[i];
    }
}

// ---------------------------------------------------------------------------
// Fortran-order gather: f[b, (x*32+y)*32+z] = primal_ch1[b, z, y, x]
// ---------------------------------------------------------------------------
__global__ void gather_f_kernel() {
    int i = blockIdx.x * blockDim.x + threadIdx.x;
    if (i >= BB*NV) return;
    int b = i / NV, v = i % NV;
    int z = v & 31, y = (v >> 5) & 31, x = v >> 10;
    g_f[i] = g_y3d[(size_t)(b*6 + 1)*NV + (z*32 + y)*32 + x];
}

// ---------------------------------------------------------------------------
// evalop1[b,j,d] = sum_v An[b,j,d,v] * f[b,v]   (one block per row, 1536 rows)
// ---------------------------------------------------------------------------
__global__ void evalop1_kernel(const float* __restrict__ An) {
    const int row = blockIdx.x;                 // (b*J + j)*D + d
    const int b   = row / PX2D;
    const float4* a = reinterpret_cast<const float4*>(An) + (size_t)row * (NV/4);
    const float4* f = reinterpret_cast<const float4*>(g_f) + (size_t)b * (NV/4);
    float acc = 0.f;
    #pragma unroll 4
    for (int i = threadIdx.x; i < NV/4; i += 256) {
        float4 av = __ldcs(a + i);
        float4 fv = f[i];
        acc = fmaf(av.x, fv.x, acc);
        acc = fmaf(av.y, fv.y, acc);
        acc = fmaf(av.z, fv.z, acc);
        acc = fmaf(av.w, fv.w, acc);
    }
    #pragma unroll
    for (int off = 16; off; off >>= 1) acc += __shfl_down_sync(0xffffffffu, acc, off);
    __shared__ float red[8];
    if ((threadIdx.x & 31) == 0) red[threadIdx.x >> 5] = acc;
    __syncthreads();
    if (threadIdx.x == 0) {
        float s = 0.f;
        #pragma unroll
        for (int i = 0; i < 8; i++) s += red[i];
        g_x2d[(size_t)(b*7 + 5)*PX2D + (row % PX2D)] = s;
    }
}

// ---------------------------------------------------------------------------
// 2D conv 3x3 SAME over (J=24, D=32). One block per (px-chunk, co, b).
// ---------------------------------------------------------------------------
template<int CIN, bool PRELU, bool RES>
__global__ void conv2d_kernel(const float* __restrict__ in, int in_ct,
                              const float* __restrict__ w,
                              const float* __restrict__ bias,
                              const float* __restrict__ alpha,
                              float* __restrict__ out, int out_ct) {
    const int b  = blockIdx.z;
    const int co = blockIdx.y;
    const int p  = blockIdx.x * 256 + threadIdx.x;   // 0..767
    __shared__ float sw[CIN*9];
    for (int i = threadIdx.x; i < CIN*9; i += 256) sw[i] = w[co*CIN*9 + i];
    __syncthreads();
    const int j = p / 32, d = p % 32;
    const float* xb = in + (size_t)b * in_ct * PX2D;
    float acc = bias[co];
    #pragma unroll 4
    for (int ci = 0; ci < CIN; ci++) {
        const float* xc = xb + ci * PX2D;
        #pragma unroll
        for (int kj = 0; kj < 3; kj++) {
            int jjj = j + kj - 1;
            if (jjj < 0 || jjj >= JJ) continue;
            #pragma unroll
            for (int kd = 0; kd < 3; kd++) {
                int ddd = d + kd - 1;
                if (ddd < 0 || ddd >= DD) continue;
                acc = fmaf(sw[ci*9 + kj*3 + kd], xc[jjj*32 + ddd], acc);
            }
        }
    }
    if (PRELU) { float a = alpha[0]; acc = acc >= 0.f ? acc : a * acc; }
    float* o = out + (size_t)(b*out_ct + co)*PX2D + p;
    if (RES) *o += acc; else *o = acc;
}

// ---------------------------------------------------------------------------
// adjoint: back[b,v] = sum_{j,d} A[b,j,v,d] * dual0[b,j,d]
// ---------------------------------------------------------------------------
__global__ void adjoint_kernel(const float* __restrict__ A) {
    __shared__ float sd[PX2D];
    const int b  = blockIdx.x / (NV/8);
    const int v0 = (blockIdx.x % (NV/8)) * 8;
    for (int i = threadIdx.x; i < PX2D; i += 256)
        sd[i] = g_x2d[(size_t)(b*7 + 0)*PX2D + i];
    __syncthreads();
    const int wrp = threadIdx.x >> 5, lane = threadIdx.x & 31;
    const int v = v0 + wrp;
    const float* Ab = A + (size_t)b * JJ * NV * DD;
    float acc = 0.f;
    #pragma unroll
    for (int j = 0; j < JJ; j++)
        acc = fmaf(__ldcs(Ab + ((size_t)j*NV + v)*DD + lane), sd[j*DD + lane], acc);
    #pragma unroll
    for (int off = 16; off; off >>= 1) acc += __shfl_down_sync(0xffffffffu, acc, off);
    if (lane == 0) {
        int z = v & 31, y = (v >> 5) & 31, x = v >> 10;
        g_y3d[(size_t)(b*6 + 5)*NV + (z*32 + y)*32 + x] = acc;
    }
}

// ---------------------------------------------------------------------------
// 3D conv 3x3x3 SAME over 32^3 using packed fma.rn.f32x2 (FFMA2).
// Block = (YR rows of one z-plane) x COPB output channels.
// Thread = XPT consecutive x outputs (XPT/2 packed f32x2 accumulators) per co.
// Input tile staged in smem with stride 36 (8B-aligned rows -> LDS.64 pairs).
// Weights staged duplicated as (w,w) float2 -> one LDS.64 = packed broadcast.
// ---------------------------------------------------------------------------
template<int CIN, int COPB, int XPT, int YR, bool PRELU, bool RES>
__global__ void __launch_bounds__((32/XPT)*YR)
conv3d_kernel(const float* __restrict__ in, int in_ct,
              const float* __restrict__ w,
              const float* __restrict__ bias,
              const float* __restrict__ alpha,
              float* __restrict__ out, int out_ct) {
    constexpr int XG    = 32 / XPT;
    constexpr int NT    = XG * YR;
    constexpr int TROWS = YR + 2;
    constexpr int TW    = 36;               // 34 used cols + 2 pad (even stride)
    constexpr int YSPL  = 32 / YR;
    constexpr int NPAIR = XPT / 2;
    constexpr int NP    = NPAIR + 1;

    extern __shared__ unsigned char sraw[];
    float* tile  = reinterpret_cast<float*>(sraw);
    float2* swt2 = reinterpret_cast<float2*>(sraw + (size_t)3*TROWS*TW*4);

    const int b   = blockIdx.z;
    const int z   = blockIdx.y;
    const int cg  = blockIdx.x / YSPL;
    const int y0  = (blockIdx.x % YSPL) * YR;
    const int tid = threadIdx.x;

    // duplicated weights
    for (int i = tid; i < COPB*CIN*27; i += NT) {
        float wv = w[(size_t)cg*COPB*CIN*27 + i];
        swt2[i] = make_float2(wv, wv);
    }

    const int xg = tid % XG;
    const int ly = tid / XG;
    const int x0 = xg * XPT;
    const int y  = y0 + ly;

    u64 acc[COPB][NPAIR];
    #pragma unroll
    for (int c = 0; c < COPB; c++)
        #pragma unroll
        for (int p = 0; p < NPAIR; p++) acc[c][p] = 0ull;

    for (int ci = 0; ci < CIN; ci++) {
        __syncthreads();
        const float* inc = in + (size_t)(b*in_ct + ci) * NV;
        for (int i = tid; i < 3*TROWS*34; i += NT) {
            int kz  = i / (TROWS*34);
            int rem = i % (TROWS*34);
            int ry  = rem / 34, rx = rem % 34;
            int zz = z + kz - 1, yy = y0 + ry - 1, xx = rx - 1;
            float v = 0.f;
            if (zz >= 0 && zz < 32 && yy >= 0 && yy < 32 && xx >= 0 && xx < 32)
                v = inc[(zz*32 + yy)*32 + xx];
            tile[(kz*TROWS + ry)*TW + rx] = v;
        }
        __syncthreads();

        #pragma unroll
        for (int kz = 0; kz < 3; kz++) {
            #pragma unroll
            for (int ky = 0; ky < 3; ky++) {
                const float* trow = &tile[(kz*TROWS + (ly + ky))*TW + x0];
                u64 P[NP];
                #pragma unroll
                for (int i = 0; i < NP; i++)
                    P[i] = *reinterpret_cast<const u64*>(trow + 2*i);   // LDS.64
                u64 Q[NPAIR];
                #pragma unroll
                for (int i = 0; i < NPAIR; i++) Q[i] = mkq(P[i], P[i+1]);
                #pragma unroll
                for (int co = 0; co < COPB; co++) {
                    const float2* wp = swt2 + (co*CIN + ci)*27 + kz*9 + ky*3;
                    u64 w0 = *reinterpret_cast<const u64*>(wp + 0);
                    u64 w1 = *reinterpret_cast<const u64*>(wp + 1);
                    u64 w2 = *reinterpret_cast<const u64*>(wp + 2);
                    #pragma unroll
                    for (int p = 0; p < NPAIR; p++) fma2(acc[co][p], w0, P[p]);
                    #pragma unroll
                    for (int p = 0; p < NPAIR; p++) fma2(acc[co][p], w1, Q[p]);
                    #pragma unroll
                    for (int p = 0; p < NPAIR; p++) fma2(acc[co][p], w2, P[p+1]);
                }
            }
        }
    }

    const float a = PRELU ? alpha[0] : 0.f;
    #pragma unroll
    for (int co = 0; co < COPB; co++) {
        const float bv = bias[cg*COPB + co];
        float* op = out + (size_t)(b*out_ct + cg*COPB + co)*NV + (z*32 + y)*32 + x0;
        #pragma unroll
        for (int p = 0; p < NPAIR; p++) {
            float lo, hi;
            unpack2(acc[co][p], lo, hi);
            float r0 = lo + bv, r1 = hi + bv;
            if (PRELU) {
                r0 = r0 >= 0.f ? r0 : a * r0;
                r1 = r1 >= 0.f ? r1 : a * r1;
            }
            if (RES) { op[2*p] += r0; op[2*p+1] += r1; }
            else     { op[2*p]  = r0; op[2*p+1]  = r1; }
        }
    }
}

// ---------------------------------------------------------------------------
// Output: primal channel 0
// ---------------------------------------------------------------------------
__global__ void out_kernel(float* __restrict__ out) {
    int i = blockIdx.x * blockDim.x + threadIdx.x;
    if (i >= BB*NV) return;
    int b = i / NV, v = i % NV;
    out[i] = g_y3d[(size_t)b*6*NV + v];
}

// ---------------------------------------------------------------------------
extern "C" void kernel_launch(void* const* d_in, const int* in_sizes, int n_in,
                              void* d_out, int out_size) {
    (void)in_sizes; (void)n_in; (void)out_size;
    const float* dual   = (const float*)d_in[0];
    const float* primal = (const float*)d_in[1];
    const float* g      = (const float*)d_in[2];
    const float* An     = (const float*)d_in[3];
    const float* A      = (const float*)d_in[4];
    const float* dw1 = (const float*)d_in[5];  const float* db1 = (const float*)d_in[6];
    const float* da1 = (const float*)d_in[7];
    const float* dw2 = (const float*)d_in[8];  const float* db2 = (const float*)d_in[9];
    const float* da2 = (const float*)d_in[10];
    const float* dw3 = (const float*)d_in[11]; const float* db3 = (const float*)d_in[12];
    const float* pw1 = (const float*)d_in[13]; const float* pb1 = (const float*)d_in[14];
    const float* pa1 = (const float*)d_in[15];
    const float* pw2 = (const float*)d_in[16]; const float* pb2 = (const float*)d_in[17];
    const float* pa2 = (const float*)d_in[18];
    const float* pw3 = (const float*)d_in[19]; const float* pb3 = (const float*)d_in[20];

    float *px2d, *ph2a, *ph2b, *py3d, *ph3a, *ph3b;
    cudaGetSymbolAddress((void**)&px2d, g_x2d);
    cudaGetSymbolAddress((void**)&ph2a, g_h2a);
    cudaGetSymbolAddress((void**)&ph2b, g_h2b);
    cudaGetSymbolAddress((void**)&py3d, g_y3d);
    cudaGetSymbolAddress((void**)&ph3a, g_h3a);
    cudaGetSymbolAddress((void**)&ph3b, g_h3b);

    // dynamic smem sizes: tile + duplicated weights
    const int SM1 = 3*34*36*4 + 8*6*27*8;    // conv1: 25056
    const int SM2 = 3*34*36*4 + 8*32*27*8;   // conv2: 69984
    const int SM3 = 3*18*36*4 + 5*32*27*8;   // conv3: 42336

    cudaFuncSetAttribute((const void*)conv3d_kernel<6, 8, 8, 32, true, false>,
                         cudaFuncAttributeMaxDynamicSharedMemorySize, SM1);
    cudaFuncSetAttribute((const void*)conv3d_kernel<32, 8, 8, 32, true, false>,
                         cudaFuncAttributeMaxDynamicSharedMemorySize, SM2);
    cudaFuncSetAttribute((const void*)conv3d_kernel<32, 5, 4, 16, false, true>,
                         cudaFuncAttributeMaxDynamicSharedMemorySize, SM3);

    init_kernel<<<(BB*5*NV + 255)/256, 256>>>(dual, g, primal);

    for (int k = 0; k < 10; k++) {
        // --- dual space ---
        gather_f_kernel<<<(BB*NV + 255)/256, 256>>>();
        evalop1_kernel<<<BB*JJ*DD, 256>>>(An);

        conv2d_kernel<7, true, false><<<dim3(3, 32, BB), 256>>>(
            px2d, 7, dw1 + (size_t)k*32*7*9, db1 + k*32, da1 + k, ph2a, 32);
        conv2d_kernel<32, true, false><<<dim3(3, 32, BB), 256>>>(
            ph2a, 32, dw2 + (size_t)k*32*32*9, db2 + k*32, da2 + k, ph2b, 32);
        conv2d_kernel<32, false, true><<<dim3(3, 5, BB), 256>>>(
            ph2b, 32, dw3 + (size_t)k*5*32*9, db3 + k*5, nullptr, px2d, 7);

        // --- adjoint ---
        adjoint_kernel<<<BB*NV/8, 256>>>(A);

        // --- primal space ---
        conv3d_kernel<6, 8, 8, 32, true, false><<<dim3(4, 32, BB), 128, SM1>>>(
            py3d, 6, pw1 + (size_t)k*32*6*27, pb1 + k*32, pa1 + k, ph3a, 32);
        conv3d_kernel<32, 8, 8, 32, true, false><<<dim3(4, 32, BB), 128, SM2>>>(
            ph3a, 32, pw2 + (size_t)k*32*32*27, pb2 + k*32, pa2 + k, ph3b, 32);
        conv3d_kernel<32, 5, 4, 16, false, true><<<dim3(2, 32, BB), 128, SM3>>>(
            ph3b, 32, pw3 + (size_t)k*5*32*27, pb3 + k*5, nullptr, py3d, 6);
    }

    out_kernel<<<(BB*NV + 255)/256, 256>>>((float*)d_out);
}

// round 3
// speedup vs baseline: 1.5777x; 1.5777x over previous
#include <cuda_runtime.h>
#include <cstdint>

// Problem constants
#define BB   2
#define JJ   24
#define DD   32
#define NV   32768           // 32*32*32
#define PX2D (JJ*DD)         // 768

// ---------------------------------------------------------------------------
// Scratch (device globals; no allocation allowed)
// ---------------------------------------------------------------------------
__device__ float g_x2d[BB*7*PX2D];   // [dual(0..4), evalop1(5), g(6)]
__device__ float g_h2a[BB*32*PX2D];
__device__ float g_h2b[BB*32*PX2D];
__device__ float g_y3d[BB*6*NV];     // [primal(0..4), evalop2(5)]
__device__ float g_h3a[BB*32*NV];
__device__ float g_h3b[BB*32*NV];
__device__ float g_f  [BB*NV];       // Fortran-flattened primal channel 1

// ---------------------------------------------------------------------------
// Init: dual -> x2d[0..4], g -> x2d[6], primal -> y3d[0..4]
// ---------------------------------------------------------------------------
__global__ void init_kernel(const float* __restrict__ dual,
                            const float* __restrict__ gg,
                            const float* __restrict__ primal) {
    int i = blockIdx.x * blockDim.x + threadIdx.x;
    if (i < BB*5*NV) {
        int b = i / (5*NV); int r = i % (5*NV); int c = r / NV; int v = r % NV;
        g_y3d[(size_t)(b*6 + c)*NV + v] = primal[i];
    }
    if (i < BB*5*PX2D) {
        int b = i / (5*PX2D); int r = i % (5*PX2D); int c = r / PX2D; int p = r % PX2D;
        g_x2d[(size_t)(b*7 + c)*PX2D + p] = dual[i];
    }
    if (i < BB*PX2D) {
        int b = i / PX2D; int p = i % PX2D;
        g_x2d[(size_t)(b*7 + 6)*PX2D + p] = gg[i];
    }
}

// ---------------------------------------------------------------------------
// Fortran-order gather: f[b, x*1024+y*32+z] = primal_ch1[b, z, y, x]
// ---------------------------------------------------------------------------
__global__ void gather_f_kernel() {
    int i = blockIdx.x * blockDim.x + threadIdx.x;
    if (i >= BB*NV) return;
    int b = i / NV, v = i % NV;
    int z = v & 31, y = (v >> 5) & 31, x = v >> 10;
    g_f[i] = g_y3d[(size_t)(b*6 + 1)*NV + (z*32 + y)*32 + x];
}

// ---------------------------------------------------------------------------
// evalop1[b,j,d] = sum_v An[b,j,d,v] * f[b,v]   (one block per row, 1536 rows)
// ---------------------------------------------------------------------------
__global__ void evalop1_kernel(const float* __restrict__ An) {
    const int row = blockIdx.x;                 // (b*J + j)*D + d
    const int b   = row / PX2D;
    const float4* a = reinterpret_cast<const float4*>(An) + (size_t)row * (NV/4);
    const float4* f = reinterpret_cast<const float4*>(g_f) + (size_t)b * (NV/4);
    float acc = 0.f;
    #pragma unroll 4
    for (int i = threadIdx.x; i < NV/4; i += 256) {
        float4 av = __ldcs(a + i);
        float4 fv = f[i];
        acc = fmaf(av.x, fv.x, acc);
        acc = fmaf(av.y, fv.y, acc);
        acc = fmaf(av.z, fv.z, acc);
        acc = fmaf(av.w, fv.w, acc);
    }
    #pragma unroll
    for (int off = 16; off; off >>= 1) acc += __shfl_down_sync(0xffffffffu, acc, off);
    __shared__ float red[8];
    if ((threadIdx.x & 31) == 0) red[threadIdx.x >> 5] = acc;
    __syncthreads();
    if (threadIdx.x == 0) {
        float s = 0.f;
        #pragma unroll
        for (int i = 0; i < 8; i++) s += red[i];
        g_x2d[(size_t)(b*7 + 5)*PX2D + (row % PX2D)] = s;
    }
}

// ---------------------------------------------------------------------------
// 2D conv 3x3 SAME over (J=24, D=32), register-blocked.
// Block = (co, b), 192 threads; thread = 4 consecutive d outputs at row j.
// ---------------------------------------------------------------------------
template<int CIN, bool PRELU, bool RES>
__global__ void __launch_bounds__(192)
conv2d_kernel(const float* __restrict__ in, int in_ct,
              const float* __restrict__ w,
              const float* __restrict__ bias,
              const float* __restrict__ alpha,
              float* __restrict__ out, int out_ct) {
    __shared__ float swt[CIN*9];
    const int co = blockIdx.x;
    const int b  = blockIdx.y;
    const int tid = threadIdx.x;
    for (int i = tid; i < CIN*9; i += 192) swt[i] = w[co*CIN*9 + i];
    __syncthreads();

    const int dg = tid & 7;        // d-chunk 0..7
    const int j  = tid >> 3;       // 0..23
    const int d0 = dg << 2;

    float acc[4] = {0.f, 0.f, 0.f, 0.f};
    const float* xb = in + (size_t)b * in_ct * PX2D;

    for (int ci = 0; ci < CIN; ci++) {
        const float* xc = xb + ci * PX2D;
        #pragma unroll
        for (int kj = 0; kj < 3; kj++) {
            const int jj = j + kj - 1;
            float r[6];
            if (jj >= 0 && jj < JJ) {
                const float* rp = xc + jj*32 + d0;
                float4 m = *reinterpret_cast<const float4*>(rp);
                r[1] = m.x; r[2] = m.y; r[3] = m.z; r[4] = m.w;
                r[0] = (d0 > 0)  ? rp[-1] : 0.f;
                r[5] = (d0 < 28) ? rp[4]  : 0.f;
            } else {
                #pragma unroll
                for (int t = 0; t < 6; t++) r[t] = 0.f;
            }
            const float* wp = &swt[ci*9 + kj*3];
            const float w0 = wp[0], w1 = wp[1], w2 = wp[2];
            #pragma unroll
            for (int di = 0; di < 4; di++)
                acc[di] = fmaf(w0, r[di], fmaf(w1, r[di+1], fmaf(w2, r[di+2], acc[di])));
        }
    }

    const float a  = PRELU ? alpha[0] : 0.f;
    const float bv = bias[co];
    float* op = out + (size_t)(b*out_ct + co)*PX2D + j*32 + d0;
    #pragma unroll
    for (int di = 0; di < 4; di++) {
        float rr = acc[di] + bv;
        if (PRELU) rr = rr >= 0.f ? rr : a * rr;
        if (RES) op[di] += rr; else op[di] = rr;
    }
}

// ---------------------------------------------------------------------------
// adjoint: back[b,v] = sum_{j,d} A[b,j,v,d] * dual0[b,j,d]
// ---------------------------------------------------------------------------
__global__ void adjoint_kernel(const float* __restrict__ A) {
    __shared__ float sd[PX2D];
    const int b  = blockIdx.x / (NV/8);
    const int v0 = (blockIdx.x % (NV/8)) * 8;
    for (int i = threadIdx.x; i < PX2D; i += 256)
        sd[i] = g_x2d[(size_t)(b*7 + 0)*PX2D + i];
    __syncthreads();
    const int wrp = threadIdx.x >> 5, lane = threadIdx.x & 31;
    const int v = v0 + wrp;
    const float* Ab = A + (size_t)b * JJ * NV * DD;
    float acc = 0.f;
    #pragma unroll
    for (int j = 0; j < JJ; j++)
        acc = fmaf(__ldcs(Ab + ((size_t)j*NV + v)*DD + lane), sd[j*DD + lane], acc);
    #pragma unroll
    for (int off = 16; off; off >>= 1) acc += __shfl_down_sync(0xffffffffu, acc, off);
    if (lane == 0) {
        int z = v & 31, y = (v >> 5) & 31, x = v >> 10;
        g_y3d[(size_t)(b*6 + 5)*NV + (z*32 + y)*32 + x] = acc;
    }
}

// ---------------------------------------------------------------------------
// 3D conv 3x3x3 SAME over 32^3, direct-from-global register blocking.
// Block = (co-group, z-plane, b), 128 threads (4 xg x 32 y).
// Thread = 8 consecutive x outputs for COPB output channels.
// Rows read straight from global (L1-resident: 3 planes = 12KB/channel).
// No smem tile, no per-ci barriers.
// ---------------------------------------------------------------------------
template<int CIN, int COPB, bool PRELU, bool RES>
__global__ void __launch_bounds__(128)
conv3d_kernel(const float* __restrict__ in, int in_ct,
              const float* __restrict__ w,
              const float* __restrict__ bias,
              const float* __restrict__ alpha,
              float* __restrict__ out, int out_ct) {
    __shared__ float swt[COPB*CIN*27];
    const int b   = blockIdx.z;
    const int z   = blockIdx.y;
    const int cg  = blockIdx.x;
    const int tid = threadIdx.x;

    for (int i = tid; i < COPB*CIN*27; i += 128)
        swt[i] = w[(size_t)cg*COPB*CIN*27 + i];
    __syncthreads();

    const int xg = tid & 3;
    const int y  = tid >> 2;
    const int x0 = xg << 3;

    float acc[COPB][8];
    #pragma unroll
    for (int c = 0; c < COPB; c++)
        #pragma unroll
        for (int xi = 0; xi < 8; xi++) acc[c][xi] = 0.f;

    for (int ci = 0; ci < CIN; ci++) {
        const float* pc = in + ((size_t)(b*in_ct + ci) << 15);
        #pragma unroll
        for (int kz = 0; kz < 3; kz++) {
            const int zz = z + kz - 1;
            if (zz < 0 || zz >= 32) continue;      // uniform per block
            #pragma unroll
            for (int ky = 0; ky < 3; ky++) {
                const int yy = y + ky - 1;
                float r[10];
                if (yy >= 0 && yy < 32) {
                    const float* rp = pc + ((zz << 5) + yy)*32 + x0;
                    float4 m0 = *reinterpret_cast<const float4*>(rp);
                    float4 m1 = *reinterpret_cast<const float4*>(rp + 4);
                    r[1] = m0.x; r[2] = m0.y; r[3] = m0.z; r[4] = m0.w;
                    r[5] = m1.x; r[6] = m1.y; r[7] = m1.z; r[8] = m1.w;
                    r[0] = (x0 > 0)  ? rp[-1] : 0.f;
                    r[9] = (x0 < 24) ? rp[8]  : 0.f;
                } else {
                    #pragma unroll
                    for (int t = 0; t < 10; t++) r[t] = 0.f;
                }
                #pragma unroll
                for (int co = 0; co < COPB; co++) {
                    const float* wp = &swt[(co*CIN + ci)*27 + kz*9 + ky*3];
                    const float w0 = wp[0], w1 = wp[1], w2 = wp[2];
                    #pragma unroll
                    for (int xi = 0; xi < 8; xi++)
                        acc[co][xi] = fmaf(w0, r[xi],
                                      fmaf(w1, r[xi+1],
                                      fmaf(w2, r[xi+2], acc[co][xi])));
                }
            }
        }
    }

    const float a = PRELU ? alpha[0] : 0.f;
    #pragma unroll
    for (int co = 0; co < COPB; co++) {
        const float bv = bias[cg*COPB + co];
        float* op = out + ((size_t)(b*out_ct + cg*COPB + co) << 15) + (z << 10) + (y << 5) + x0;
        #pragma unroll
        for (int xi = 0; xi < 8; xi++) {
            float rr = acc[co][xi] + bv;
            if (PRELU) rr = rr >= 0.f ? rr : a * rr;
            if (RES) op[xi] += rr; else op[xi] = rr;
        }
    }
}

// ---------------------------------------------------------------------------
// Output: primal channel 0
// ---------------------------------------------------------------------------
__global__ void out_kernel(float* __restrict__ out) {
    int i = blockIdx.x * blockDim.x + threadIdx.x;
    if (i >= BB*NV) return;
    int b = i / NV, v = i % NV;
    out[i] = g_y3d[(size_t)b*6*NV + v];
}

// ---------------------------------------------------------------------------
extern "C" void kernel_launch(void* const* d_in, const int* in_sizes, int n_in,
                              void* d_out, int out_size) {
    (void)in_sizes; (void)n_in; (void)out_size;
    const float* dual   = (const float*)d_in[0];
    const float* primal = (const float*)d_in[1];
    const float* g      = (const float*)d_in[2];
    const float* An     = (const float*)d_in[3];
    const float* A      = (const float*)d_in[4];
    const float* dw1 = (const float*)d_in[5];  const float* db1 = (const float*)d_in[6];
    const float* da1 = (const float*)d_in[7];
    const float* dw2 = (const float*)d_in[8];  const float* db2 = (const float*)d_in[9];
    const float* da2 = (const float*)d_in[10];
    const float* dw3 = (const float*)d_in[11]; const float* db3 = (const float*)d_in[12];
    const float* pw1 = (const float*)d_in[13]; const float* pb1 = (const float*)d_in[14];
    const float* pa1 = (const float*)d_in[15];
    const float* pw2 = (const float*)d_in[16]; const float* pb2 = (const float*)d_in[17];
    const float* pa2 = (const float*)d_in[18];
    const float* pw3 = (const float*)d_in[19]; const float* pb3 = (const float*)d_in[20];

    float *px2d, *ph2a, *ph2b, *py3d, *ph3a, *ph3b;
    cudaGetSymbolAddress((void**)&px2d, g_x2d);
    cudaGetSymbolAddress((void**)&ph2a, g_h2a);
    cudaGetSymbolAddress((void**)&ph2b, g_h2b);
    cudaGetSymbolAddress((void**)&py3d, g_y3d);
    cudaGetSymbolAddress((void**)&ph3a, g_h3a);
    cudaGetSymbolAddress((void**)&ph3b, g_h3b);

    init_kernel<<<(BB*5*NV + 255)/256, 256>>>(dual, g, primal);

    for (int k = 0; k < 10; k++) {
        // --- dual space ---
        gather_f_kernel<<<(BB*NV + 255)/256, 256>>>();
        evalop1_kernel<<<BB*JJ*DD, 256>>>(An);

        conv2d_kernel<7, true, false><<<dim3(32, BB), 192>>>(
            px2d, 7, dw1 + (size_t)k*32*7*9, db1 + k*32, da1 + k, ph2a, 32);
        conv2d_kernel<32, true, false><<<dim3(32, BB), 192>>>(
            ph2a, 32, dw2 + (size_t)k*32*32*9, db2 + k*32, da2 + k, ph2b, 32);
        conv2d_kernel<32, false, true><<<dim3(5, BB), 192>>>(
            ph2b, 32, dw3 + (size_t)k*5*32*9, db3 + k*5, nullptr, px2d, 7);

        // --- adjoint ---
        adjoint_kernel<<<BB*NV/8, 256>>>(A);

        // --- primal space ---
        conv3d_kernel<6, 4, true, false><<<dim3(8, 32, BB), 128>>>(
            py3d, 6, pw1 + (size_t)k*32*6*27, pb1 + k*32, pa1 + k, ph3a, 32);
        conv3d_kernel<32, 4, true, false><<<dim3(8, 32, BB), 128>>>(
            ph3a, 32, pw2 + (size_t)k*32*32*27, pb2 + k*32, pa2 + k, ph3b, 32);
        conv3d_kernel<32, 1, false, true><<<dim3(5, 32, BB), 128>>>(
            ph3b, 32, pw3 + (size_t)k*5*32*27, pb3 + k*5, nullptr, py3d, 6);
    }

    out_kernel<<<(BB*NV + 255)/256, 256>>>((float*)d_out);
}